// round 12
// baseline (speedup 1.0000x reference)
#include <cuda_runtime.h>
#include <cuda_bf16.h>
#include <cuda_fp16.h>
#include <cstdint>

#define B_SZ     2
#define N_IN     50000
#define N_OUT    12500
#define NNZ      500000
#define IN_C     256
#define OUT_C    256
#define M_ROWS   (B_SZ * N_OUT)   // 25000
#define CAP      128               // padded bucket capacity per row (mean 40)

// ---------------- scratch (device globals; no allocation allowed) ------------
__device__ int    g_counts[N_OUT];
__device__ float2 g_epad[(size_t)N_OUT * CAP];          // padded edge buckets
__device__ __half g_xh[(size_t)B_SZ * N_IN * IN_C];     // x in fp16 (51.2 MB)
__device__ __nv_bfloat16 g_axh[(size_t)M_ROWS * IN_C];  // AX hi (bf16)
__device__ __nv_bfloat16 g_axl[(size_t)M_ROWS * IN_C];  // AX lo (bf16)
__device__ __nv_bfloat16 g_wh[(size_t)OUT_C * IN_C];    // W^T hi: [n][k]
__device__ __nv_bfloat16 g_wl[(size_t)OUT_C * IN_C];    // W^T lo: [n][k]

// ---------------- bucket build ------------------------------------------------
__global__ void k_zero_counts() {
    int i = blockIdx.x * blockDim.x + threadIdx.x;
    if (i < N_OUT) g_counts[i] = 0;
}

__global__ void k_fill_pad(const int* __restrict__ rows,
                           const int* __restrict__ cols,
                           const float* __restrict__ vals) {
    int e = blockIdx.x * blockDim.x + threadIdx.x;
    if (e < NNZ) {
        int r = rows[e];
        int p = atomicAdd(&g_counts[r], 1);
        if (p > CAP - 1) p = CAP - 1;   // statistically unreachable; bounds safety
        float2 ed;
        ed.x = __int_as_float(cols[e]);
        ed.y = vals[e];
        g_epad[(size_t)r * CAP + p] = ed;
    }
}

// ---------------- x -> fp16 streaming conversion (16 floats/thread) ----------
__global__ __launch_bounds__(256) void k_xhalf(const float4* __restrict__ x4) {
    size_t i = (size_t)blockIdx.x * blockDim.x + threadIdx.x;
    float4 a0 = x4[4 * i];
    float4 a1 = x4[4 * i + 1];
    float4 a2 = x4[4 * i + 2];
    float4 a3 = x4[4 * i + 3];
    __half2 h0 = __floats2half2_rn(a0.x, a0.y);
    __half2 h1 = __floats2half2_rn(a0.z, a0.w);
    __half2 h2 = __floats2half2_rn(a1.x, a1.y);
    __half2 h3 = __floats2half2_rn(a1.z, a1.w);
    __half2 h4 = __floats2half2_rn(a2.x, a2.y);
    __half2 h5 = __floats2half2_rn(a2.z, a2.w);
    __half2 h6 = __floats2half2_rn(a3.x, a3.y);
    __half2 h7 = __floats2half2_rn(a3.z, a3.w);
    uint4 o0, o1;
    o0.x = *reinterpret_cast<uint32_t*>(&h0);
    o0.y = *reinterpret_cast<uint32_t*>(&h1);
    o0.z = *reinterpret_cast<uint32_t*>(&h2);
    o0.w = *reinterpret_cast<uint32_t*>(&h3);
    o1.x = *reinterpret_cast<uint32_t*>(&h4);
    o1.y = *reinterpret_cast<uint32_t*>(&h5);
    o1.z = *reinterpret_cast<uint32_t*>(&h6);
    o1.w = *reinterpret_cast<uint32_t*>(&h7);
    *reinterpret_cast<uint4*>(&g_xh[i * 16])     = o0;
    *reinterpret_cast<uint4*>(&g_xh[i * 16 + 8]) = o1;
}

// ---------------- W split/transpose: g_wh/g_wl[n][k] = split(W[k][n]) --------
__global__ void k_wsplit(const float* __restrict__ W) {
    int idx = blockIdx.x * blockDim.x + threadIdx.x;
    if (idx < IN_C * OUT_C) {
        int k = idx >> 8;
        int n = idx & 255;
        float w = W[idx];
        __nv_bfloat16 h = __float2bfloat16(w);
        __nv_bfloat16 l = __float2bfloat16(w - __bfloat162float(h));
        g_wh[(size_t)n * IN_C + k] = h;
        g_wl[(size_t)n * IN_C + k] = l;
    }
}

// ---------------- SpMM v5: both batches per block, fp16 gathers --------------
__device__ __forceinline__ void fma8(float4& a, float4& b, float s, const uint4& h) {
    float2 f0 = __half22float2(*reinterpret_cast<const __half2*>(&h.x));
    float2 f1 = __half22float2(*reinterpret_cast<const __half2*>(&h.y));
    float2 f2 = __half22float2(*reinterpret_cast<const __half2*>(&h.z));
    float2 f3 = __half22float2(*reinterpret_cast<const __half2*>(&h.w));
    a.x = fmaf(s, f0.x, a.x);
    a.y = fmaf(s, f0.y, a.y);
    a.z = fmaf(s, f1.x, a.z);
    a.w = fmaf(s, f1.y, a.w);
    b.x = fmaf(s, f2.x, b.x);
    b.y = fmaf(s, f2.y, b.y);
    b.z = fmaf(s, f3.x, b.z);
    b.w = fmaf(s, f3.y, b.w);
}

__global__ __launch_bounds__(256) void k_spmm() {
    int row   = blockIdx.x;
    int tid   = threadIdx.x;
    int eslot = tid >> 5;          // 0..7
    int cg    = tid & 31;          // channel group (8 halves = 16 B)

    __shared__ float4 sred[2][2][8][32];   // [batch][half(lo4/hi4)][slot][cg]

    int cnt = g_counts[row];
    if (cnt > CAP) cnt = CAP;
    const float2* __restrict__ ep = g_epad + (size_t)row * CAP;
    const __half* __restrict__ xb0 = g_xh + (size_t)cg * 8;
    const __half* __restrict__ xb1 = g_xh + (size_t)N_IN * IN_C + cg * 8;

    float4 a00 = make_float4(0.f, 0.f, 0.f, 0.f);
    float4 b00 = a00, a10 = a00, b10 = a00;
    float4 a01 = a00, b01 = a00, a11 = a00, b11 = a00;

    int j = eslot;
    for (; j + 8 < cnt; j += 16) {
        float2 e0 = ep[j];
        float2 e1 = ep[j + 8];
        size_t o0 = (size_t)__float_as_int(e0.x) * IN_C;
        size_t o1 = (size_t)__float_as_int(e1.x) * IN_C;
        uint4 h00 = *reinterpret_cast<const uint4*>(xb0 + o0);
        uint4 h10 = *reinterpret_cast<const uint4*>(xb1 + o0);
        uint4 h01 = *reinterpret_cast<const uint4*>(xb0 + o1);
        uint4 h11 = *reinterpret_cast<const uint4*>(xb1 + o1);
        fma8(a00, b00, e0.y, h00);
        fma8(a10, b10, e0.y, h10);
        fma8(a01, b01, e1.y, h01);
        fma8(a11, b11, e1.y, h11);
    }
    if (j < cnt) {
        float2 e0 = ep[j];
        size_t o0 = (size_t)__float_as_int(e0.x) * IN_C;
        uint4 h00 = *reinterpret_cast<const uint4*>(xb0 + o0);
        uint4 h10 = *reinterpret_cast<const uint4*>(xb1 + o0);
        fma8(a00, b00, e0.y, h00);
        fma8(a10, b10, e0.y, h10);
    }
    a00.x += a01.x; a00.y += a01.y; a00.z += a01.z; a00.w += a01.w;
    b00.x += b01.x; b00.y += b01.y; b00.z += b01.z; b00.w += b01.w;
    a10.x += a11.x; a10.y += a11.y; a10.z += a11.z; a10.w += a11.w;
    b10.x += b11.x; b10.y += b11.y; b10.z += b11.z; b10.w += b11.w;

    sred[0][0][eslot][cg] = a00;
    sred[0][1][eslot][cg] = b00;
    sred[1][0][eslot][cg] = a10;
    sred[1][1][eslot][cg] = b10;
    __syncthreads();

    int cg2 = tid >> 3;            // 0..31
    int ch  = tid & 7;             // 0..7
    int hsel = ch >> 2;
    int lch  = ch & 3;
#pragma unroll
    for (int b = 0; b < 2; b++) {
        const float* src = reinterpret_cast<const float*>(&sred[b][hsel][0][0]) + cg2 * 4 + lch;
        float v = 0.f;
#pragma unroll
        for (int e = 0; e < 8; e++) v += src[e * 128];
        __nv_bfloat16 h = __float2bfloat16(v);
        __nv_bfloat16 l = __float2bfloat16(v - __bfloat162float(h));
        size_t ofs = ((size_t)b * N_OUT + row) * IN_C + cg2 * 8 + ch;
        g_axh[ofs] = h;
        g_axl[ofs] = l;
    }
}

// ---------------- bf16 MMA GEMM, double-buffered smem + ldmatrix -------------
#define GBM 128
#define GBN 64
#define GBK 32
#define APAD 40   // 80B row stride: conflict-free ldmatrix
#define NCHUNK (IN_C / GBK)   // 8

// per-buffer element offsets (bf16 elems)
#define OFF_AH 0
#define OFF_AL (GBM * APAD)                 // 5120
#define OFF_BH (2 * GBM * APAD)             // 10240
#define OFF_BL (2 * GBM * APAD + GBN * APAD) // 12800
#define BUF_ELEMS (2 * GBM * APAD + 2 * GBN * APAD)   // 15360
#define SMEM_BYTES (2 * BUF_ELEMS * 2)                 // 61440

#define MMA_BF16(c, a0, a1, a2, a3, b0, b1)                                   \
    asm volatile(                                                             \
        "mma.sync.aligned.m16n8k16.row.col.f32.bf16.bf16.f32 "                \
        "{%0,%1,%2,%3},{%4,%5,%6,%7},{%8,%9},{%0,%1,%2,%3};"                  \
        : "+f"((c)[0]), "+f"((c)[1]), "+f"((c)[2]), "+f"((c)[3])              \
        : "r"(a0), "r"(a1), "r"(a2), "r"(a3), "r"(b0), "r"(b1))

#define LDSM_X4(r, addr)                                                      \
    asm volatile("ldmatrix.sync.aligned.m8n8.x4.shared.b16 {%0,%1,%2,%3}, [%4];" \
        : "=r"((r)[0]), "=r"((r)[1]), "=r"((r)[2]), "=r"((r)[3]) : "r"(addr))

__global__ __launch_bounds__(256) void k_gemm_mma(const float* __restrict__ bias,
                                                  float* __restrict__ C) {
    extern __shared__ __nv_bfloat16 smg[];

    int tid  = threadIdx.x;
    int wid  = tid >> 5;
    int lane = tid & 31;
    int gid  = lane >> 2;
    int tig  = lane & 3;

    int m0 = blockIdx.y * GBM;
    int n0 = blockIdx.x * GBN;
    int warp_m = (wid >> 1) * 32;
    int warp_n = (wid & 1) * 32;

    int ld_row = (lane & 7) | (((lane >> 3) & 1) << 3);   // 0..15
    int ld_k   = (lane >> 4) << 3;                        // 0 or 8

    uint32_t u0 = (uint32_t)__cvta_generic_to_shared(&smg[0]);

    float acc[2][4][4];
#pragma unroll
    for (int i = 0; i < 2; i++)
#pragma unroll
        for (int j = 0; j < 4; j++)
#pragma unroll
            for (int k = 0; k < 4; k++) acc[i][j][k] = 0.f;

    int a_r = tid >> 2;
    int a_c = (tid & 3) * 8;
    int b_r = tid >> 2;
    int b_c = (tid & 3) * 8;

    const uint4 z4 = make_uint4(0u, 0u, 0u, 0u);
    uint4 pah[2], pal[2], pbh, pbl;

    int gr0 = m0 + a_r;
    int gr1 = m0 + a_r + 64;
    bool ok0 = (gr0 < M_ROWS);
    bool ok1 = (gr1 < M_ROWS);
    const __nv_bfloat16* pAh0 = &g_axh[(size_t)gr0 * IN_C + a_c];
    const __nv_bfloat16* pAh1 = &g_axh[(size_t)gr1 * IN_C + a_c];
    const __nv_bfloat16* pAl0 = &g_axl[(size_t)gr0 * IN_C + a_c];
    const __nv_bfloat16* pAl1 = &g_axl[(size_t)gr1 * IN_C + a_c];
    const __nv_bfloat16* pBh  = &g_wh[(size_t)(n0 + b_r) * IN_C + b_c];
    const __nv_bfloat16* pBl  = &g_wl[(size_t)(n0 + b_r) * IN_C + b_c];

    // prefetch chunk 0 and stage into buffer 0
    pah[0] = ok0 ? *reinterpret_cast<const uint4*>(pAh0) : z4;
    pah[1] = ok1 ? *reinterpret_cast<const uint4*>(pAh1) : z4;
    pal[0] = ok0 ? *reinterpret_cast<const uint4*>(pAl0) : z4;
    pal[1] = ok1 ? *reinterpret_cast<const uint4*>(pAl1) : z4;
    pbh    = *reinterpret_cast<const uint4*>(pBh);
    pbl    = *reinterpret_cast<const uint4*>(pBl);
    {
        __nv_bfloat16* base = smg;   // buffer 0
        *reinterpret_cast<uint4*>(base + OFF_AH + a_r * APAD + a_c)        = pah[0];
        *reinterpret_cast<uint4*>(base + OFF_AH + (a_r + 64) * APAD + a_c) = pah[1];
        *reinterpret_cast<uint4*>(base + OFF_AL + a_r * APAD + a_c)        = pal[0];
        *reinterpret_cast<uint4*>(base + OFF_AL + (a_r + 64) * APAD + a_c) = pal[1];
        *reinterpret_cast<uint4*>(base + OFF_BH + b_r * APAD + b_c)        = pbh;
        *reinterpret_cast<uint4*>(base + OFF_BL + b_r * APAD + b_c)        = pbl;
    }
    __syncthreads();

    for (int kc = 0; kc < NCHUNK; kc++) {
        int cur = kc & 1;
        int nxt = cur ^ 1;
        uint32_t ubase = u0 + (uint32_t)(cur * BUF_ELEMS) * 2;

        // prefetch next chunk from global
        if (kc + 1 < NCHUNK) {
            int kb = (kc + 1) * GBK;
            pah[0] = ok0 ? *reinterpret_cast<const uint4*>(pAh0 + kb) : z4;
            pah[1] = ok1 ? *reinterpret_cast<const uint4*>(pAh1 + kb) : z4;
            pal[0] = ok0 ? *reinterpret_cast<const uint4*>(pAl0 + kb) : z4;
            pal[1] = ok1 ? *reinterpret_cast<const uint4*>(pAl1 + kb) : z4;
            pbh    = *reinterpret_cast<const uint4*>(pBh + kb);
            pbl    = *reinterpret_cast<const uint4*>(pBl + kb);
        }

        // compute on current buffer
#pragma unroll
        for (int ks = 0; ks < GBK / 16; ks++) {
            int kk = ks * 16;
            uint32_t ah[2][4], al[2][4];
#pragma unroll
            for (int mf = 0; mf < 2; mf++) {
                uint32_t offA = (uint32_t)((warp_m + mf * 16 + ld_row) * APAD + kk + ld_k) * 2;
                LDSM_X4(ah[mf], ubase + OFF_AH * 2 + offA);
                LDSM_X4(al[mf], ubase + OFF_AL * 2 + offA);
            }
            uint32_t bh[2][4], bl[2][4];
#pragma unroll
            for (int p = 0; p < 2; p++) {
                uint32_t offB = (uint32_t)((warp_n + p * 16 + ld_row) * APAD + kk + ld_k) * 2;
                LDSM_X4(bh[p], ubase + OFF_BH * 2 + offB);
                LDSM_X4(bl[p], ubase + OFF_BL * 2 + offB);
            }
#pragma unroll
            for (int nf = 0; nf < 4; nf++) {
                int p = nf >> 1;
                int s = nf & 1;
                uint32_t bh0 = bh[p][s], bh1 = bh[p][s + 2];
                uint32_t bl0 = bl[p][s], bl1 = bl[p][s + 2];
#pragma unroll
                for (int mf = 0; mf < 2; mf++) {
                    MMA_BF16(acc[mf][nf], ah[mf][0], ah[mf][1], ah[mf][2], ah[mf][3], bh0, bh1);
                    MMA_BF16(acc[mf][nf], ah[mf][0], ah[mf][1], ah[mf][2], ah[mf][3], bl0, bl1);
                    MMA_BF16(acc[mf][nf], al[mf][0], al[mf][1], al[mf][2], al[mf][3], bh0, bh1);
                }
            }
        }

        // stage next chunk into the other buffer
        if (kc + 1 < NCHUNK) {
            __nv_bfloat16* base = smg + nxt * BUF_ELEMS;
            *reinterpret_cast<uint4*>(base + OFF_AH + a_r * APAD + a_c)        = pah[0];
            *reinterpret_cast<uint4*>(base + OFF_AH + (a_r + 64) * APAD + a_c) = pah[1];
            *reinterpret_cast<uint4*>(base + OFF_AL + a_r * APAD + a_c)        = pal[0];
            *reinterpret_cast<uint4*>(base + OFF_AL + (a_r + 64) * APAD + a_c) = pal[1];
            *reinterpret_cast<uint4*>(base + OFF_BH + b_r * APAD + b_c)        = pbh;
            *reinterpret_cast<uint4*>(base + OFF_BL + b_r * APAD + b_c)        = pbl;
        }
        __syncthreads();
    }

#pragma unroll
    for (int mf = 0; mf < 2; mf++) {
        int row0 = m0 + warp_m + mf * 16 + gid;
#pragma unroll
        for (int half = 0; half < 2; half++) {
            int row = row0 + half * 8;
            if (row >= M_ROWS) continue;
            int brow = (row >= N_OUT) ? row - N_OUT : row;
#pragma unroll
            for (int nf = 0; nf < 4; nf++) {
                int col = n0 + warp_n + nf * 8 + tig * 2;
                float2 bb = *reinterpret_cast<const float2*>(bias + (size_t)brow * OUT_C + col);
                float2 o;
                o.x = acc[mf][nf][half * 2 + 0] + bb.x;
                o.y = acc[mf][nf][half * 2 + 1] + bb.y;
                *reinterpret_cast<float2*>(C + (size_t)row * OUT_C + col) = o;
            }
        }
    }
}

// ---------------- launch -----------------------------------------------------
extern "C" void kernel_launch(void* const* d_in, const int* in_sizes, int n_in,
                              void* d_out, int out_size) {
    const float* x      = (const float*)d_in[0];
    const int*   rows   = (const int*)d_in[1];
    const int*   cols   = (const int*)d_in[2];
    const float* vals   = (const float*)d_in[3];
    const float* weight = (const float*)d_in[4];
    const float* bias   = (const float*)d_in[5];
    float*       out    = (float*)d_out;

    cudaFuncSetAttribute(k_gemm_mma, cudaFuncAttributeMaxDynamicSharedMemorySize, SMEM_BYTES);

    k_zero_counts<<<(N_OUT + 255) / 256, 256>>>();
    k_xhalf<<<(B_SZ * N_IN * IN_C / 16 + 255) / 256, 256>>>((const float4*)x);
    k_fill_pad<<<(NNZ + 255) / 256, 256>>>(rows, cols, vals);
    k_wsplit<<<(IN_C * OUT_C + 255) / 256, 256>>>(weight);

    k_spmm<<<N_OUT, 256>>>();

    dim3 ggrid(OUT_C / GBN, (M_ROWS + GBM - 1) / GBM);
    k_gemm_mma<<<ggrid, 256, SMEM_BYTES>>>(bias, out);
}

// round 13
// speedup vs baseline: 1.1939x; 1.1939x over previous
#include <cuda_runtime.h>
#include <cuda_bf16.h>
#include <cuda_fp16.h>
#include <cstdint>

#define B_SZ     2
#define N_IN     50000
#define N_OUT    12500
#define NNZ      500000
#define IN_C     256
#define OUT_C    256
#define M_ROWS   (B_SZ * N_OUT)   // 25000
#define CAP      128               // padded bucket capacity per row (mean 40)
#define WSCALE   4096.0f           // exact power of 2; keeps W in fp16 normal range
#define WINV     (1.0f / 4096.0f)

// ---------------- scratch (device globals; no allocation allowed) ------------
__device__ int    g_counts[N_OUT];
__device__ float2 g_epad[(size_t)N_OUT * CAP];          // padded edge buckets
__device__ __half g_xh[(size_t)B_SZ * N_IN * IN_C];     // x in fp16 (51.2 MB)
__device__ __half g_axf[(size_t)M_ROWS * IN_C];         // AX in fp16 (12.8 MB)
__device__ __half g_wf[(size_t)OUT_C * IN_C];           // W^T * 4096, fp16: [n][k]

// ---------------- bucket build ------------------------------------------------
__global__ void k_zero_counts() {
    int i = blockIdx.x * blockDim.x + threadIdx.x;
    if (i < N_OUT) g_counts[i] = 0;
}

__global__ void k_fill_pad(const int* __restrict__ rows,
                           const int* __restrict__ cols,
                           const float* __restrict__ vals) {
    int e = blockIdx.x * blockDim.x + threadIdx.x;
    if (e < NNZ) {
        int r = rows[e];
        int p = atomicAdd(&g_counts[r], 1);
        if (p > CAP - 1) p = CAP - 1;   // statistically unreachable; bounds safety
        float2 ed;
        ed.x = __int_as_float(cols[e]);
        ed.y = vals[e];
        g_epad[(size_t)r * CAP + p] = ed;
    }
}

// ---------------- x -> fp16 streaming conversion (16 floats/thread) ----------
__global__ __launch_bounds__(256) void k_xhalf(const float4* __restrict__ x4) {
    size_t i = (size_t)blockIdx.x * blockDim.x + threadIdx.x;
    float4 a0 = x4[4 * i];
    float4 a1 = x4[4 * i + 1];
    float4 a2 = x4[4 * i + 2];
    float4 a3 = x4[4 * i + 3];
    __half2 h0 = __floats2half2_rn(a0.x, a0.y);
    __half2 h1 = __floats2half2_rn(a0.z, a0.w);
    __half2 h2 = __floats2half2_rn(a1.x, a1.y);
    __half2 h3 = __floats2half2_rn(a1.z, a1.w);
    __half2 h4 = __floats2half2_rn(a2.x, a2.y);
    __half2 h5 = __floats2half2_rn(a2.z, a2.w);
    __half2 h6 = __floats2half2_rn(a3.x, a3.y);
    __half2 h7 = __floats2half2_rn(a3.z, a3.w);
    uint4 o0, o1;
    o0.x = *reinterpret_cast<uint32_t*>(&h0);
    o0.y = *reinterpret_cast<uint32_t*>(&h1);
    o0.z = *reinterpret_cast<uint32_t*>(&h2);
    o0.w = *reinterpret_cast<uint32_t*>(&h3);
    o1.x = *reinterpret_cast<uint32_t*>(&h4);
    o1.y = *reinterpret_cast<uint32_t*>(&h5);
    o1.z = *reinterpret_cast<uint32_t*>(&h6);
    o1.w = *reinterpret_cast<uint32_t*>(&h7);
    *reinterpret_cast<uint4*>(&g_xh[i * 16])     = o0;
    *reinterpret_cast<uint4*>(&g_xh[i * 16 + 8]) = o1;
}

// ---------------- W split/transpose: g_wf[n][k] = fp16(W[k][n] * 4096) -------
__global__ void k_wsplit(const float* __restrict__ W) {
    int idx = blockIdx.x * blockDim.x + threadIdx.x;
    if (idx < IN_C * OUT_C) {
        int k = idx >> 8;
        int n = idx & 255;
        g_wf[(size_t)n * IN_C + k] = __float2half(W[idx] * WSCALE);
    }
}

// ---------------- SpMM: both batches per block, fp16 gathers -----------------
__device__ __forceinline__ void fma8(float4& a, float4& b, float s, const uint4& h) {
    float2 f0 = __half22float2(*reinterpret_cast<const __half2*>(&h.x));
    float2 f1 = __half22float2(*reinterpret_cast<const __half2*>(&h.y));
    float2 f2 = __half22float2(*reinterpret_cast<const __half2*>(&h.z));
    float2 f3 = __half22float2(*reinterpret_cast<const __half2*>(&h.w));
    a.x = fmaf(s, f0.x, a.x);
    a.y = fmaf(s, f0.y, a.y);
    a.z = fmaf(s, f1.x, a.z);
    a.w = fmaf(s, f1.y, a.w);
    b.x = fmaf(s, f2.x, b.x);
    b.y = fmaf(s, f2.y, b.y);
    b.z = fmaf(s, f3.x, b.z);
    b.w = fmaf(s, f3.y, b.w);
}

__global__ __launch_bounds__(256) void k_spmm() {
    int row   = blockIdx.x;
    int tid   = threadIdx.x;
    int eslot = tid >> 5;          // 0..7
    int cg    = tid & 31;          // channel group (8 halves = 16 B)

    __shared__ float4 sred[2][2][8][32];   // [batch][half(lo4/hi4)][slot][cg]

    int cnt = g_counts[row];
    if (cnt > CAP) cnt = CAP;
    const float2* __restrict__ ep = g_epad + (size_t)row * CAP;
    const __half* __restrict__ xb0 = g_xh + (size_t)cg * 8;
    const __half* __restrict__ xb1 = g_xh + (size_t)N_IN * IN_C + cg * 8;

    float4 a00 = make_float4(0.f, 0.f, 0.f, 0.f);
    float4 b00 = a00, a10 = a00, b10 = a00;
    float4 a01 = a00, b01 = a00, a11 = a00, b11 = a00;

    int j = eslot;
    for (; j + 8 < cnt; j += 16) {
        float2 e0 = ep[j];
        float2 e1 = ep[j + 8];
        size_t o0 = (size_t)__float_as_int(e0.x) * IN_C;
        size_t o1 = (size_t)__float_as_int(e1.x) * IN_C;
        uint4 h00 = *reinterpret_cast<const uint4*>(xb0 + o0);
        uint4 h10 = *reinterpret_cast<const uint4*>(xb1 + o0);
        uint4 h01 = *reinterpret_cast<const uint4*>(xb0 + o1);
        uint4 h11 = *reinterpret_cast<const uint4*>(xb1 + o1);
        fma8(a00, b00, e0.y, h00);
        fma8(a10, b10, e0.y, h10);
        fma8(a01, b01, e1.y, h01);
        fma8(a11, b11, e1.y, h11);
    }
    if (j < cnt) {
        float2 e0 = ep[j];
        size_t o0 = (size_t)__float_as_int(e0.x) * IN_C;
        uint4 h00 = *reinterpret_cast<const uint4*>(xb0 + o0);
        uint4 h10 = *reinterpret_cast<const uint4*>(xb1 + o0);
        fma8(a00, b00, e0.y, h00);
        fma8(a10, b10, e0.y, h10);
    }
    a00.x += a01.x; a00.y += a01.y; a00.z += a01.z; a00.w += a01.w;
    b00.x += b01.x; b00.y += b01.y; b00.z += b01.z; b00.w += b01.w;
    a10.x += a11.x; a10.y += a11.y; a10.z += a11.z; a10.w += a11.w;
    b10.x += b11.x; b10.y += b11.y; b10.z += b11.z; b10.w += b11.w;

    sred[0][0][eslot][cg] = a00;
    sred[0][1][eslot][cg] = b00;
    sred[1][0][eslot][cg] = a10;
    sred[1][1][eslot][cg] = b10;
    __syncthreads();

    int cg2 = tid >> 3;            // 0..31
    int ch  = tid & 7;             // 0..7
    int hsel = ch >> 2;
    int lch  = ch & 3;
#pragma unroll
    for (int b = 0; b < 2; b++) {
        const float* src = reinterpret_cast<const float*>(&sred[b][hsel][0][0]) + cg2 * 4 + lch;
        float v = 0.f;
#pragma unroll
        for (int e = 0; e < 8; e++) v += src[e * 128];
        size_t ofs = ((size_t)b * N_OUT + row) * IN_C + cg2 * 8 + ch;
        g_axf[ofs] = __float2half(v);
    }
}

// ---------------- fp16 MMA GEMM, double-buffered smem + ldmatrix -------------
#define GBM 128
#define GBN 64
#define GBK 32
#define APAD 40   // 80B row stride: conflict-free ldmatrix
#define NCHUNK (IN_C / GBK)   // 8

// per-buffer element offsets (fp16 elems)
#define OFF_A 0
#define OFF_B (GBM * APAD)                       // 5120
#define BUF_ELEMS (GBM * APAD + GBN * APAD)      // 7680
#define SMEM_BYTES (2 * BUF_ELEMS * 2)           // 30720

#define MMA_F16(c, a0, a1, a2, a3, b0, b1)                                    \
    asm volatile(                                                             \
        "mma.sync.aligned.m16n8k16.row.col.f32.f16.f16.f32 "                  \
        "{%0,%1,%2,%3},{%4,%5,%6,%7},{%8,%9},{%0,%1,%2,%3};"                  \
        : "+f"((c)[0]), "+f"((c)[1]), "+f"((c)[2]), "+f"((c)[3])              \
        : "r"(a0), "r"(a1), "r"(a2), "r"(a3), "r"(b0), "r"(b1))

#define LDSM_X4(r, addr)                                                      \
    asm volatile("ldmatrix.sync.aligned.m8n8.x4.shared.b16 {%0,%1,%2,%3}, [%4];" \
        : "=r"((r)[0]), "=r"((r)[1]), "=r"((r)[2]), "=r"((r)[3]) : "r"(addr))

__global__ __launch_bounds__(256) void k_gemm_mma(const float* __restrict__ bias,
                                                  float* __restrict__ C) {
    extern __shared__ __half smg[];

    int tid  = threadIdx.x;
    int wid  = tid >> 5;
    int lane = tid & 31;
    int gid  = lane >> 2;
    int tig  = lane & 3;

    int m0 = blockIdx.y * GBM;
    int n0 = blockIdx.x * GBN;
    int warp_m = (wid >> 1) * 32;
    int warp_n = (wid & 1) * 32;

    int ld_row = (lane & 7) | (((lane >> 3) & 1) << 3);   // 0..15
    int ld_k   = (lane >> 4) << 3;                        // 0 or 8

    uint32_t u0 = (uint32_t)__cvta_generic_to_shared(&smg[0]);

    float acc[2][4][4];
#pragma unroll
    for (int i = 0; i < 2; i++)
#pragma unroll
        for (int j = 0; j < 4; j++)
#pragma unroll
            for (int k = 0; k < 4; k++) acc[i][j][k] = 0.f;

    int a_r = tid >> 2;
    int a_c = (tid & 3) * 8;
    int b_r = tid >> 2;
    int b_c = (tid & 3) * 8;

    const uint4 z4 = make_uint4(0u, 0u, 0u, 0u);
    uint4 pa[2], pb;

    int gr0 = m0 + a_r;
    int gr1 = m0 + a_r + 64;
    bool ok0 = (gr0 < M_ROWS);
    bool ok1 = (gr1 < M_ROWS);
    const __half* pA0 = &g_axf[(size_t)gr0 * IN_C + a_c];
    const __half* pA1 = &g_axf[(size_t)gr1 * IN_C + a_c];
    const __half* pB  = &g_wf[(size_t)(n0 + b_r) * IN_C + b_c];

    // prefetch chunk 0 and stage into buffer 0
    pa[0] = ok0 ? *reinterpret_cast<const uint4*>(pA0) : z4;
    pa[1] = ok1 ? *reinterpret_cast<const uint4*>(pA1) : z4;
    pb    = *reinterpret_cast<const uint4*>(pB);
    {
        __half* base = smg;   // buffer 0
        *reinterpret_cast<uint4*>(base + OFF_A + a_r * APAD + a_c)        = pa[0];
        *reinterpret_cast<uint4*>(base + OFF_A + (a_r + 64) * APAD + a_c) = pa[1];
        *reinterpret_cast<uint4*>(base + OFF_B + b_r * APAD + b_c)        = pb;
    }
    __syncthreads();

    for (int kc = 0; kc < NCHUNK; kc++) {
        int cur = kc & 1;
        int nxt = cur ^ 1;
        uint32_t ubase = u0 + (uint32_t)(cur * BUF_ELEMS) * 2;

        // prefetch next chunk from global
        if (kc + 1 < NCHUNK) {
            int kb = (kc + 1) * GBK;
            pa[0] = ok0 ? *reinterpret_cast<const uint4*>(pA0 + kb) : z4;
            pa[1] = ok1 ? *reinterpret_cast<const uint4*>(pA1 + kb) : z4;
            pb    = *reinterpret_cast<const uint4*>(pB + kb);
        }

        // compute on current buffer
#pragma unroll
        for (int ks = 0; ks < GBK / 16; ks++) {
            int kk = ks * 16;
            uint32_t af[2][4];
#pragma unroll
            for (int mf = 0; mf < 2; mf++) {
                uint32_t offA = (uint32_t)((warp_m + mf * 16 + ld_row) * APAD + kk + ld_k) * 2;
                LDSM_X4(af[mf], ubase + OFF_A * 2 + offA);
            }
            uint32_t bf[2][4];
#pragma unroll
            for (int p = 0; p < 2; p++) {
                uint32_t offB = (uint32_t)((warp_n + p * 16 + ld_row) * APAD + kk + ld_k) * 2;
                LDSM_X4(bf[p], ubase + OFF_B * 2 + offB);
            }
#pragma unroll
            for (int nf = 0; nf < 4; nf++) {
                int p = nf >> 1;
                int s = nf & 1;
                uint32_t b0 = bf[p][s], b1 = bf[p][s + 2];
#pragma unroll
                for (int mf = 0; mf < 2; mf++) {
                    MMA_F16(acc[mf][nf], af[mf][0], af[mf][1], af[mf][2], af[mf][3], b0, b1);
                }
            }
        }

        // stage next chunk into the other buffer
        if (kc + 1 < NCHUNK) {
            __half* base = smg + nxt * BUF_ELEMS;
            *reinterpret_cast<uint4*>(base + OFF_A + a_r * APAD + a_c)        = pa[0];
            *reinterpret_cast<uint4*>(base + OFF_A + (a_r + 64) * APAD + a_c) = pa[1];
            *reinterpret_cast<uint4*>(base + OFF_B + b_r * APAD + b_c)        = pb;
        }
        __syncthreads();
    }

#pragma unroll
    for (int mf = 0; mf < 2; mf++) {
        int row0 = m0 + warp_m + mf * 16 + gid;
#pragma unroll
        for (int half = 0; half < 2; half++) {
            int row = row0 + half * 8;
            if (row >= M_ROWS) continue;
            int brow = (row >= N_OUT) ? row - N_OUT : row;
#pragma unroll
            for (int nf = 0; nf < 4; nf++) {
                int col = n0 + warp_n + nf * 8 + tig * 2;
                float2 bb = *reinterpret_cast<const float2*>(bias + (size_t)brow * OUT_C + col);
                float2 o;
                o.x = acc[mf][nf][half * 2 + 0] * WINV + bb.x;
                o.y = acc[mf][nf][half * 2 + 1] * WINV + bb.y;
                *reinterpret_cast<float2*>(C + (size_t)row * OUT_C + col) = o;
            }
        }
    }
}

// ---------------- launch -----------------------------------------------------
extern "C" void kernel_launch(void* const* d_in, const int* in_sizes, int n_in,
                              void* d_out, int out_size) {
    const float* x      = (const float*)d_in[0];
    const int*   rows   = (const int*)d_in[1];
    const int*   cols   = (const int*)d_in[2];
    const float* vals   = (const float*)d_in[3];
    const float* weight = (const float*)d_in[4];
    const float* bias   = (const float*)d_in[5];
    float*       out    = (float*)d_out;

    cudaFuncSetAttribute(k_gemm_mma, cudaFuncAttributeMaxDynamicSharedMemorySize, SMEM_BYTES);

    k_zero_counts<<<(N_OUT + 255) / 256, 256>>>();
    k_xhalf<<<(B_SZ * N_IN * IN_C / 16 + 255) / 256, 256>>>((const float4*)x);
    k_fill_pad<<<(NNZ + 255) / 256, 256>>>(rows, cols, vals);
    k_wsplit<<<(IN_C * OUT_C + 255) / 256, 256>>>(weight);

    k_spmm<<<N_OUT, 256>>>();

    dim3 ggrid(OUT_C / GBN, (M_ROWS + GBM - 1) / GBM);
    k_gemm_mma<<<ggrid, 256, SMEM_BYTES>>>(bias, out);
}